// round 1
// baseline (speedup 1.0000x reference)
#include <cuda_runtime.h>
#include <cuda_bf16.h>
#include <cstdint>

// Problem constants (fixed shapes for this problem)
#define N_TOK 8192     // D*H*W = 8*32*32
#define BATCH 2
#define CC 96          // base channels
#define CV 288         // 3*CC
#define KIN 320        // 128 (context) + 96 (h0) + 96 (h1)

// ---------------------------------------------------------------------------
// Device scratch (no allocations allowed anywhere)
// ---------------------------------------------------------------------------
__device__ __nv_bfloat16 g_Wks[CC * KIN];          // combined weights for ksum
__device__ float         g_bks[CC];
__device__ __nv_bfloat16 g_Wv[CV * KIN];           // combined weights for v
__device__ float         g_bv[CV];
__device__ __nv_bfloat16 g_Wq[CC * CC];            // W5 cast
__device__ __nv_bfloat16 g_W6c[CC * CV];           // W6 cast
__device__ __nv_bfloat16 g_ksum[(size_t)BATCH * N_TOK * CC];   // [B, N, 96] token-major
__device__ __nv_bfloat16 g_q[(size_t)BATCH * N_TOK * CC];      // [B, N, 96] token-major
__device__ __nv_bfloat16 g_v[(size_t)BATCH * CV * N_TOK];      // [B, 288, N] channel-major
__device__ __nv_bfloat16 g_res[(size_t)BATCH * N_TOK * CV];    // [B, N, 288] token-major

// ---------------------------------------------------------------------------
// Helpers
// ---------------------------------------------------------------------------
__device__ __forceinline__ uint32_t ld32bf(const __nv_bfloat16* p) {
    return *reinterpret_cast<const uint32_t*>(p);
}

__device__ __forceinline__ void mma_bf16(float& d0, float& d1, float& d2, float& d3,
                                         uint32_t a0, uint32_t a1, uint32_t a2, uint32_t a3,
                                         uint32_t b0, uint32_t b1)
{
    asm volatile(
        "mma.sync.aligned.m16n8k16.row.col.f32.bf16.bf16.f32 "
        "{%0,%1,%2,%3}, {%4,%5,%6,%7}, {%8,%9}, {%0,%1,%2,%3};\n"
        : "+f"(d0), "+f"(d1), "+f"(d2), "+f"(d3)
        : "r"(a0), "r"(a1), "r"(a2), "r"(a3), "r"(b0), "r"(b1));
}

// ---------------------------------------------------------------------------
// Prep kernel: build combined weights on device (graph-capturable, cheap)
//   k = W3a@W1 @ ctx + W3b@W2 @ hcat + kbias ; ksum folds the x3 q-tiling
//   v = W4a@W1 @ ctx + W4b@W2 @ hcat + vbias
// ---------------------------------------------------------------------------
__global__ void prep_kernel(const float* __restrict__ W1, const float* __restrict__ b1,
                            const float* __restrict__ W2, const float* __restrict__ b2,
                            const float* __restrict__ W3, const float* __restrict__ b3,
                            const float* __restrict__ W4, const float* __restrict__ b4,
                            const float* __restrict__ W5, const float* __restrict__ W6)
{
    const int O_WKS = 0;
    const int O_WV  = O_WKS + CC * KIN;      // 30720
    const int O_BKS = O_WV + CV * KIN;       // 122880
    const int O_BV  = O_BKS + CC;            // 122976
    const int O_WQ  = O_BV + CV;             // 123264
    const int O_W6  = O_WQ + CC * CC;        // 132480
    const int TOT   = O_W6 + CC * CV;        // 160128

    for (int t = blockIdx.x * blockDim.x + threadIdx.x; t < TOT;
         t += gridDim.x * blockDim.x) {
        if (t < O_WV) {
            // Wks[c][i]
            int c = t / KIN, i = t % KIN;
            float acc = 0.f;
            if (i < 128) {
                #pragma unroll 1
                for (int r = 0; r < 3; r++) {
                    const float* w3 = W3 + (c + 96 * r) * 288;
                    for (int j = 0; j < 192; j++) acc += w3[j] * W1[j * 128 + i];
                }
            } else {
                int ih = i - 128;  // column of hcat (0..191)
                #pragma unroll 1
                for (int r = 0; r < 3; r++) {
                    const float* w3 = W3 + (c + 96 * r) * 288 + 192;
                    for (int j = 0; j < 96; j++) acc += w3[j] * W2[j * 192 + ih];
                }
            }
            g_Wks[t] = __float2bfloat16(acc);
        } else if (t < O_BKS) {
            // Wv[c][i]
            int u = t - O_WV;
            int c = u / KIN, i = u % KIN;
            float acc = 0.f;
            if (i < 128) {
                const float* w4 = W4 + c * 288;
                for (int j = 0; j < 192; j++) acc += w4[j] * W1[j * 128 + i];
            } else {
                int ih = i - 128;
                const float* w4 = W4 + c * 288 + 192;
                for (int j = 0; j < 96; j++) acc += w4[j] * W2[j * 192 + ih];
            }
            g_Wv[u] = __float2bfloat16(acc);
        } else if (t < O_BV) {
            int c = t - O_BKS;
            float acc = 0.f;
            for (int r = 0; r < 3; r++) {
                int row = c + 96 * r;
                acc += b3[row];
                const float* w3 = W3 + row * 288;
                for (int j = 0; j < 192; j++) acc += w3[j] * b1[j];
                for (int j = 0; j < 96; j++)  acc += w3[192 + j] * b2[j];
            }
            g_bks[c] = acc;
        } else if (t < O_WQ) {
            int c = t - O_BV;
            float acc = b4[c];
            const float* w4 = W4 + c * 288;
            for (int j = 0; j < 192; j++) acc += w4[j] * b1[j];
            for (int j = 0; j < 96; j++)  acc += w4[192 + j] * b2[j];
            g_bv[c] = acc;
        } else if (t < O_W6) {
            int u = t - O_WQ;
            g_Wq[u] = __float2bfloat16(W5[u]);
        } else {
            int u = t - O_W6;
            g_W6c[u] = __float2bfloat16(W6[u]);
        }
    }
}

// ---------------------------------------------------------------------------
// Projection GEMM: out[M, token-tile] = W[M,K] @ X[K,N] + bias
//   X comes from up to 3 concatenated fp32 channel-major sources.
//   TOKMAJOR=true  -> out bf16 [B, N, M]   (for ksum, q)
//   TOKMAJOR=false -> out bf16 [B, M, N]   (for v)
// CTA: 128 threads (4 warps), 64 tokens; warp handles 16 tokens x M.
// ---------------------------------------------------------------------------
template<int M, int K, bool TOKMAJOR>
__global__ void __launch_bounds__(128) proj_kernel(
    const float* __restrict__ s0, int k0,
    const float* __restrict__ s1, int k1,
    const float* __restrict__ s2,
    const __nv_bfloat16* __restrict__ W,
    const float* __restrict__ bias,
    __nv_bfloat16* __restrict__ out)
{
    __shared__ __nv_bfloat16 sX[64 * 40];  // [n(64)][k(32)+pad8]

    const int tid = threadIdx.x;
    const int warp = tid >> 5;
    const int lane = tid & 31;
    const int t4 = lane >> 2;
    const int tm4 = lane & 3;
    const int b = blockIdx.y;
    const int n0 = blockIdx.x * 64;
    const int rw = warp * 16;

    const float* p0 = s0 + (size_t)b * k0 * N_TOK;
    const float* p1 = s1 + (size_t)b * k1 * N_TOK;
    const float* p2 = s2 + (size_t)b * (K - k0 - k1) * N_TOK;

    constexpr int MT = M / 8;
    float acc[MT][4];
    #pragma unroll
    for (int i = 0; i < MT; i++) { acc[i][0]=0.f; acc[i][1]=0.f; acc[i][2]=0.f; acc[i][3]=0.f; }

    for (int kc = 0; kc < K; kc += 32) {
        // cooperative load + transpose + fp32->bf16: [32 k][64 n] -> sX[n][k]
        #pragma unroll
        for (int it = 0; it < 16; it++) {
            int idx = it * 128 + tid;
            int k = idx >> 6;
            int n = idx & 63;
            int r = kc + k;
            float v;
            if (r < k0)            v = p0[(size_t)r * N_TOK + n0 + n];
            else if (r < k0 + k1)  v = p1[(size_t)(r - k0) * N_TOK + n0 + n];
            else                   v = p2[(size_t)(r - k0 - k1) * N_TOK + n0 + n];
            sX[n * 40 + k] = __float2bfloat16(v);
        }
        __syncthreads();

        #pragma unroll
        for (int ks = 0; ks < 2; ks++) {
            const __nv_bfloat16* qb = sX + (rw + t4) * 40 + ks * 16 + 2 * tm4;
            uint32_t a0 = ld32bf(qb);
            uint32_t a1 = ld32bf(qb + 8 * 40);
            uint32_t a2 = ld32bf(qb + 8);
            uint32_t a3 = ld32bf(qb + 8 * 40 + 8);
            #pragma unroll
            for (int mt = 0; mt < MT; mt++) {
                const __nv_bfloat16* wb = W + (size_t)(mt * 8 + t4) * K + kc + ks * 16 + 2 * tm4;
                uint32_t b0 = ld32bf(wb);
                uint32_t b1 = ld32bf(wb + 8);
                mma_bf16(acc[mt][0], acc[mt][1], acc[mt][2], acc[mt][3],
                         a0, a1, a2, a3, b0, b1);
            }
        }
        __syncthreads();
    }

    // epilogue
    int row0 = n0 + rw + t4;
    #pragma unroll
    for (int mt = 0; mt < MT; mt++) {
        int o = mt * 8 + 2 * tm4;
        float bz0 = bias[o], bz1 = bias[o + 1];
        float v0 = acc[mt][0] + bz0;
        float v1 = acc[mt][1] + bz1;
        float v2 = acc[mt][2] + bz0;
        float v3 = acc[mt][3] + bz1;
        if (TOKMAJOR) {
            *reinterpret_cast<__nv_bfloat162*>(out + ((size_t)(b * N_TOK + row0)) * M + o) =
                __floats2bfloat162_rn(v0, v1);
            *reinterpret_cast<__nv_bfloat162*>(out + ((size_t)(b * N_TOK + row0 + 8)) * M + o) =
                __floats2bfloat162_rn(v2, v3);
        } else {
            out[((size_t)(b * M + o)) * N_TOK + row0]         = __float2bfloat16(v0);
            out[((size_t)(b * M + o + 1)) * N_TOK + row0]     = __float2bfloat16(v1);
            out[((size_t)(b * M + o)) * N_TOK + row0 + 8]     = __float2bfloat16(v2);
            out[((size_t)(b * M + o + 1)) * N_TOK + row0 + 8] = __float2bfloat16(v3);
        }
    }
}

// ---------------------------------------------------------------------------
// Flash attention kernel.
//   S[n,m] = sum_c q[n,c]*ksum[m,c]   (K=96, logits are tiny -> max-free softmax)
//   res[n,c] = (sum_m exp(S) * v[c,m]) / (sum_m exp(S))
// CTA: 4 warps, 64 Q rows; loop over 128 KV tiles of 64.
// smem: sQ[64][104], sK[64][104], sV[288][72]  (bf16) = 68096 B
// ---------------------------------------------------------------------------
__global__ void __launch_bounds__(128, 1) flash_kernel(
    const __nv_bfloat16* __restrict__ qt,    // [B, N, 96]
    const __nv_bfloat16* __restrict__ kst,   // [B, N, 96]
    const __nv_bfloat16* __restrict__ vv,    // [B, 288, N]
    __nv_bfloat16* __restrict__ rest)        // [B, N, 288]
{
    extern __shared__ __nv_bfloat16 smem[];
    __nv_bfloat16* sQ = smem;                    // 64*104
    __nv_bfloat16* sK = smem + 64 * 104;         // 64*104
    __nv_bfloat16* sV = smem + 2 * 64 * 104;     // 288*72

    const int tid = threadIdx.x;
    const int warp = tid >> 5;
    const int lane = tid & 31;
    const int t4 = lane >> 2;
    const int tm4 = lane & 3;
    const int b = blockIdx.y;
    const int n0 = blockIdx.x * 64;
    const int rw = warp * 16;

    // load Q tile [64][96] -> sQ[n][c] (row stride 104)
    #pragma unroll
    for (int it = 0; it < 6; it++) {
        int idx = it * 128 + tid;
        int row = idx / 12;
        int c8 = idx % 12;
        *reinterpret_cast<uint4*>(sQ + row * 104 + c8 * 8) =
            *reinterpret_cast<const uint4*>(qt + ((size_t)(b * N_TOK + n0 + row)) * 96 + c8 * 8);
    }

    float o_[36][4];
    #pragma unroll
    for (int i = 0; i < 36; i++) { o_[i][0]=0.f; o_[i][1]=0.f; o_[i][2]=0.f; o_[i][3]=0.f; }
    float l0 = 0.f, l1 = 0.f;

    for (int mt_i = 0; mt_i < N_TOK / 64; mt_i++) {
        int m0 = mt_i * 64;
        // load Ksum tile [64][96] -> sK[m][c]
        #pragma unroll
        for (int it = 0; it < 6; it++) {
            int idx = it * 128 + tid;
            int row = idx / 12;
            int c8 = idx % 12;
            *reinterpret_cast<uint4*>(sK + row * 104 + c8 * 8) =
                *reinterpret_cast<const uint4*>(kst + ((size_t)(b * N_TOK + m0 + row)) * 96 + c8 * 8);
        }
        // load V tile [288][64] -> sV[c][m]
        #pragma unroll
        for (int it = 0; it < 18; it++) {
            int idx = it * 128 + tid;
            int c = idx >> 3;
            int q8 = idx & 7;
            *reinterpret_cast<uint4*>(sV + c * 72 + q8 * 8) =
                *reinterpret_cast<const uint4*>(vv + ((size_t)(b * CV + c)) * N_TOK + m0 + q8 * 8);
        }
        __syncthreads();

        // S = Q @ Ksum^T : per warp 16 rows x 64 cols
        float s[8][4];
        #pragma unroll
        for (int j = 0; j < 8; j++) { s[j][0]=0.f; s[j][1]=0.f; s[j][2]=0.f; s[j][3]=0.f; }
        #pragma unroll
        for (int kk = 0; kk < 6; kk++) {
            const __nv_bfloat16* qb = sQ + (rw + t4) * 104 + kk * 16 + 2 * tm4;
            uint32_t a0 = ld32bf(qb);
            uint32_t a1 = ld32bf(qb + 8 * 104);
            uint32_t a2 = ld32bf(qb + 8);
            uint32_t a3 = ld32bf(qb + 8 * 104 + 8);
            #pragma unroll
            for (int j = 0; j < 8; j++) {
                const __nv_bfloat16* kb = sK + (j * 8 + t4) * 104 + kk * 16 + 2 * tm4;
                uint32_t b0 = ld32bf(kb);
                uint32_t b1 = ld32bf(kb + 8);
                mma_bf16(s[j][0], s[j][1], s[j][2], s[j][3], a0, a1, a2, a3, b0, b1);
            }
        }

        // P = exp(S), accumulate row sums, repack as A fragments (bf16)
        #pragma unroll
        for (int j = 0; j < 8; j++) {
            s[j][0] = __expf(s[j][0]);
            s[j][1] = __expf(s[j][1]);
            s[j][2] = __expf(s[j][2]);
            s[j][3] = __expf(s[j][3]);
            l0 += s[j][0] + s[j][1];
            l1 += s[j][2] + s[j][3];
        }
        uint32_t pa[4][4];
        #pragma unroll
        for (int g = 0; g < 4; g++) {
            __nv_bfloat162 t0 = __floats2bfloat162_rn(s[2 * g][0], s[2 * g][1]);
            __nv_bfloat162 t1 = __floats2bfloat162_rn(s[2 * g][2], s[2 * g][3]);
            __nv_bfloat162 t2 = __floats2bfloat162_rn(s[2 * g + 1][0], s[2 * g + 1][1]);
            __nv_bfloat162 t3 = __floats2bfloat162_rn(s[2 * g + 1][2], s[2 * g + 1][3]);
            pa[g][0] = *reinterpret_cast<uint32_t*>(&t0);
            pa[g][1] = *reinterpret_cast<uint32_t*>(&t1);
            pa[g][2] = *reinterpret_cast<uint32_t*>(&t2);
            pa[g][3] = *reinterpret_cast<uint32_t*>(&t3);
        }

        // O += P @ V^T : per warp 16 rows x 288 cols
        #pragma unroll
        for (int g = 0; g < 4; g++) {
            #pragma unroll
            for (int ct = 0; ct < 36; ct++) {
                const __nv_bfloat16* vb = sV + (ct * 8 + t4) * 72 + g * 16 + 2 * tm4;
                uint32_t b0 = ld32bf(vb);
                uint32_t b1 = ld32bf(vb + 8);
                mma_bf16(o_[ct][0], o_[ct][1], o_[ct][2], o_[ct][3],
                         pa[g][0], pa[g][1], pa[g][2], pa[g][3], b0, b1);
            }
        }
        __syncthreads();
    }

    // finalize: reduce row sums across the quad, normalize, store bf16
    l0 += __shfl_xor_sync(0xffffffffu, l0, 1);
    l0 += __shfl_xor_sync(0xffffffffu, l0, 2);
    l1 += __shfl_xor_sync(0xffffffffu, l1, 1);
    l1 += __shfl_xor_sync(0xffffffffu, l1, 2);
    float inv0 = 1.f / l0;
    float inv1 = 1.f / l1;

    size_t row0 = (size_t)(b * N_TOK + n0 + rw + t4);
    #pragma unroll
    for (int ct = 0; ct < 36; ct++) {
        int c = ct * 8 + 2 * tm4;
        *reinterpret_cast<__nv_bfloat162*>(rest + row0 * CV + c) =
            __floats2bfloat162_rn(o_[ct][0] * inv0, o_[ct][1] * inv0);
        *reinterpret_cast<__nv_bfloat162*>(rest + (row0 + 8) * CV + c) =
            __floats2bfloat162_rn(o_[ct][2] * inv1, o_[ct][3] * inv1);
    }
}

// ---------------------------------------------------------------------------
// Final kernel: out[o,n] = sum_c W6[o,c]*res[n,c] + b6[o] + x[o,n]   (fp32 out)
// A fragments straight from gmem (res token-major), B from W6 (L1-cached).
// ---------------------------------------------------------------------------
__global__ void __launch_bounds__(128) final_kernel(
    const __nv_bfloat16* __restrict__ rest,  // [B, N, 288]
    const __nv_bfloat16* __restrict__ W6,    // [96, 288] bf16
    const float* __restrict__ b6,
    const float* __restrict__ x,             // [B, 96, N]
    float* __restrict__ out)                 // [B, 96, N]
{
    const int tid = threadIdx.x;
    const int warp = tid >> 5;
    const int lane = tid & 31;
    const int t4 = lane >> 2;
    const int tm4 = lane & 3;
    const int b = blockIdx.y;
    const int n0 = blockIdx.x * 64;
    const int rw = warp * 16;

    float acc[12][4];
    #pragma unroll
    for (int i = 0; i < 12; i++) { acc[i][0]=0.f; acc[i][1]=0.f; acc[i][2]=0.f; acc[i][3]=0.f; }

    const __nv_bfloat16* r0p = rest + ((size_t)(b * N_TOK + n0 + rw + t4)) * CV;
    const __nv_bfloat16* r1p = r0p + (size_t)8 * CV;

    #pragma unroll
    for (int ks = 0; ks < 18; ks++) {
        uint32_t a0 = ld32bf(r0p + ks * 16 + 2 * tm4);
        uint32_t a1 = ld32bf(r1p + ks * 16 + 2 * tm4);
        uint32_t a2 = ld32bf(r0p + ks * 16 + 2 * tm4 + 8);
        uint32_t a3 = ld32bf(r1p + ks * 16 + 2 * tm4 + 8);
        #pragma unroll
        for (int mt = 0; mt < 12; mt++) {
            const __nv_bfloat16* wb = W6 + (size_t)(mt * 8 + t4) * CV + ks * 16 + 2 * tm4;
            uint32_t b0 = ld32bf(wb);
            uint32_t b1 = ld32bf(wb + 8);
            mma_bf16(acc[mt][0], acc[mt][1], acc[mt][2], acc[mt][3],
                     a0, a1, a2, a3, b0, b1);
        }
    }

    int n = n0 + rw + t4;
    #pragma unroll
    for (int mt = 0; mt < 12; mt++) {
        int o = mt * 8 + 2 * tm4;
        size_t i00 = ((size_t)(b * CC + o)) * N_TOK + n;
        size_t i01 = i00 + N_TOK;
        out[i00]     = acc[mt][0] + b6[o]     + x[i00];
        out[i01]     = acc[mt][1] + b6[o + 1] + x[i01];
        out[i00 + 8] = acc[mt][2] + b6[o]     + x[i00 + 8];
        out[i01 + 8] = acc[mt][3] + b6[o + 1] + x[i01 + 8];
    }
}

// ---------------------------------------------------------------------------
// Launch
// ---------------------------------------------------------------------------
extern "C" void kernel_launch(void* const* d_in, const int* in_sizes, int n_in,
                              void* d_out, int out_size)
{
    const float* context = (const float*)d_in[0];
    const float* h0 = (const float*)d_in[1];
    const float* h1 = (const float*)d_in[2];
    const float* x  = (const float*)d_in[3];
    const float* W1 = (const float*)d_in[4];
    const float* b1 = (const float*)d_in[5];
    const float* W2 = (const float*)d_in[6];
    const float* b2 = (const float*)d_in[7];
    const float* W3 = (const float*)d_in[8];
    const float* b3 = (const float*)d_in[9];
    const float* W4 = (const float*)d_in[10];
    const float* b4 = (const float*)d_in[11];
    const float* W5 = (const float*)d_in[12];
    const float* b5 = (const float*)d_in[13];
    const float* W6 = (const float*)d_in[14];
    const float* b6 = (const float*)d_in[15];
    float* out = (float*)d_out;

    // resolve device scratch addresses
    void *pWks, *pBks, *pWv, *pBv, *pWq, *pW6, *pKsum, *pQ, *pV, *pRes;
    cudaGetSymbolAddress(&pWks, g_Wks);
    cudaGetSymbolAddress(&pBks, g_bks);
    cudaGetSymbolAddress(&pWv, g_Wv);
    cudaGetSymbolAddress(&pBv, g_bv);
    cudaGetSymbolAddress(&pWq, g_Wq);
    cudaGetSymbolAddress(&pW6, g_W6c);
    cudaGetSymbolAddress(&pKsum, g_ksum);
    cudaGetSymbolAddress(&pQ, g_q);
    cudaGetSymbolAddress(&pV, g_v);
    cudaGetSymbolAddress(&pRes, g_res);

    static_assert(2 * 64 * 104 + 288 * 72 == 34048, "smem layout");
    const int FLASH_SMEM = 34048 * 2;  // 68096 bytes
    cudaFuncSetAttribute(flash_kernel, cudaFuncAttributeMaxDynamicSharedMemorySize, FLASH_SMEM);

    prep_kernel<<<640, 256>>>(W1, b1, W2, b2, W3, b3, W4, b4, W5, W6);

    dim3 grid(N_TOK / 64, BATCH);
    proj_kernel<CC, KIN, true><<<grid, 128>>>(
        context, 128, h0, 96, h1,
        (const __nv_bfloat16*)pWks, (const float*)pBks, (__nv_bfloat16*)pKsum);
    proj_kernel<CV, KIN, false><<<grid, 128>>>(
        context, 128, h0, 96, h1,
        (const __nv_bfloat16*)pWv, (const float*)pBv, (__nv_bfloat16*)pV);
    proj_kernel<CC, CC, true><<<grid, 128>>>(
        x, 96, x, 0, x,
        (const __nv_bfloat16*)pWq, b5, (__nv_bfloat16*)pQ);

    flash_kernel<<<grid, 128, FLASH_SMEM>>>(
        (const __nv_bfloat16*)pQ, (const __nv_bfloat16*)pKsum,
        (const __nv_bfloat16*)pV, (__nv_bfloat16*)pRes);

    final_kernel<<<grid, 128>>>(
        (const __nv_bfloat16*)pRes, (const __nv_bfloat16*)pW6, b6, x, out);
}

// round 3
// speedup vs baseline: 1.2122x; 1.2122x over previous
#include <cuda_runtime.h>
#include <cuda_bf16.h>
#include <cstdint>

// Problem constants (fixed shapes)
#define N_TOK 8192     // D*H*W = 8*32*32
#define BATCH 2
#define CC 96          // base channels
#define CV 288         // 3*CC
#define KIN 320        // 128 (context) + 96 (h0) + 96 (h1)

// ---------------------------------------------------------------------------
// Device scratch (no allocations allowed anywhere)
// ---------------------------------------------------------------------------
__device__ __align__(128) __nv_bfloat16 g_Wks[CC * KIN];
__device__ float         g_bks[CC];
__device__ __align__(128) __nv_bfloat16 g_Wv[CV * KIN];
__device__ float         g_bv[CV];
__device__ __align__(128) __nv_bfloat16 g_Wq[CC * CC];
__device__ __align__(128) __nv_bfloat16 g_W6c[CC * CV];
__device__ __align__(128) __nv_bfloat16 g_ksum[(size_t)BATCH * N_TOK * CC];  // [B, N, 96]
__device__ __align__(128) __nv_bfloat16 g_q[(size_t)BATCH * N_TOK * CC];     // [B, N, 96]
__device__ __align__(128) __nv_bfloat16 g_v[(size_t)BATCH * CV * N_TOK];     // [B, 288, N]

// ---------------------------------------------------------------------------
// Helpers
// ---------------------------------------------------------------------------
__device__ __forceinline__ uint32_t ld32bf(const __nv_bfloat16* p) {
    return *reinterpret_cast<const uint32_t*>(p);
}

__device__ __forceinline__ void mma_bf16(float& d0, float& d1, float& d2, float& d3,
                                         uint32_t a0, uint32_t a1, uint32_t a2, uint32_t a3,
                                         uint32_t b0, uint32_t b1)
{
    asm volatile(
        "mma.sync.aligned.m16n8k16.row.col.f32.bf16.bf16.f32 "
        "{%0,%1,%2,%3}, {%4,%5,%6,%7}, {%8,%9}, {%0,%1,%2,%3};\n"
        : "+f"(d0), "+f"(d1), "+f"(d2), "+f"(d3)
        : "r"(a0), "r"(a1), "r"(a2), "r"(a3), "r"(b0), "r"(b1));
}

__device__ __forceinline__ void ldsm4(uint32_t addr, uint32_t& r0, uint32_t& r1,
                                      uint32_t& r2, uint32_t& r3)
{
    asm volatile("ldmatrix.sync.aligned.m8n8.x4.shared.b16 {%0,%1,%2,%3}, [%4];\n"
                 : "=r"(r0), "=r"(r1), "=r"(r2), "=r"(r3) : "r"(addr));
}

__device__ __forceinline__ void cp16(uint32_t smem_dst, const void* gsrc)
{
    asm volatile("cp.async.cg.shared.global [%0], [%1], 16;\n"
                 :: "r"(smem_dst), "l"(gsrc));
}
__device__ __forceinline__ void cp_commit() { asm volatile("cp.async.commit_group;\n"); }
__device__ __forceinline__ void cp_wait0()  { asm volatile("cp.async.wait_group 0;\n"); }

// ---------------------------------------------------------------------------
// Prep kernel: build combined weights on device
//   ksum = sum_r W3[r-block] @ [W1; W2],  v = W4 @ [W1; W2]  (1x1 conv algebra)
// ---------------------------------------------------------------------------
__global__ void prep_kernel(const float* __restrict__ W1, const float* __restrict__ b1,
                            const float* __restrict__ W2, const float* __restrict__ b2,
                            const float* __restrict__ W3, const float* __restrict__ b3,
                            const float* __restrict__ W4, const float* __restrict__ b4,
                            const float* __restrict__ W5, const float* __restrict__ W6)
{
    const int O_WKS = 0;
    const int O_WV  = O_WKS + CC * KIN;
    const int O_BKS = O_WV + CV * KIN;
    const int O_BV  = O_BKS + CC;
    const int O_WQ  = O_BV + CV;
    const int O_W6  = O_WQ + CC * CC;
    const int TOT   = O_W6 + CC * CV;

    for (int t = blockIdx.x * blockDim.x + threadIdx.x; t < TOT;
         t += gridDim.x * blockDim.x) {
        if (t < O_WV) {
            int c = t / KIN, i = t % KIN;
            float acc = 0.f;
            if (i < 128) {
                #pragma unroll 1
                for (int r = 0; r < 3; r++) {
                    const float* w3 = W3 + (c + 96 * r) * 288;
                    for (int j = 0; j < 192; j++) acc += w3[j] * W1[j * 128 + i];
                }
            } else {
                int ih = i - 128;
                #pragma unroll 1
                for (int r = 0; r < 3; r++) {
                    const float* w3 = W3 + (c + 96 * r) * 288 + 192;
                    for (int j = 0; j < 96; j++) acc += w3[j] * W2[j * 192 + ih];
                }
            }
            g_Wks[t] = __float2bfloat16(acc);
        } else if (t < O_BKS) {
            int u = t - O_WV;
            int c = u / KIN, i = u % KIN;
            float acc = 0.f;
            if (i < 128) {
                const float* w4 = W4 + c * 288;
                for (int j = 0; j < 192; j++) acc += w4[j] * W1[j * 128 + i];
            } else {
                int ih = i - 128;
                const float* w4 = W4 + c * 288 + 192;
                for (int j = 0; j < 96; j++) acc += w4[j] * W2[j * 192 + ih];
            }
            g_Wv[u] = __float2bfloat16(acc);
        } else if (t < O_BV) {
            int c = t - O_BKS;
            float acc = 0.f;
            for (int r = 0; r < 3; r++) {
                int row = c + 96 * r;
                acc += b3[row];
                const float* w3 = W3 + row * 288;
                for (int j = 0; j < 192; j++) acc += w3[j] * b1[j];
                for (int j = 0; j < 96; j++)  acc += w3[192 + j] * b2[j];
            }
            g_bks[c] = acc;
        } else if (t < O_WQ) {
            int c = t - O_BV;
            float acc = b4[c];
            const float* w4 = W4 + c * 288;
            for (int j = 0; j < 192; j++) acc += w4[j] * b1[j];
            for (int j = 0; j < 96; j++)  acc += w4[192 + j] * b2[j];
            g_bv[c] = acc;
        } else if (t < O_W6) {
            int u = t - O_WQ;
            g_Wq[u] = __float2bfloat16(W5[u]);
        } else {
            int u = t - O_W6;
            g_W6c[u] = __float2bfloat16(W6[u]);
        }
    }
}

// ---------------------------------------------------------------------------
// Projection GEMM: out = W[M,K] @ X[K,token-tile] + bias
// ---------------------------------------------------------------------------
template<int M, int K, bool TOKMAJOR>
__global__ void __launch_bounds__(128) proj_kernel(
    const float* __restrict__ s0, int k0,
    const float* __restrict__ s1, int k1,
    const float* __restrict__ s2,
    const __nv_bfloat16* __restrict__ W,
    const float* __restrict__ bias,
    __nv_bfloat16* __restrict__ out)
{
    __shared__ __nv_bfloat16 sX[64 * 40];

    const int tid = threadIdx.x;
    const int warp = tid >> 5;
    const int lane = tid & 31;
    const int t4 = lane >> 2;
    const int tm4 = lane & 3;
    const int b = blockIdx.y;
    const int n0 = blockIdx.x * 64;
    const int rw = warp * 16;

    const float* p0 = s0 + (size_t)b * k0 * N_TOK;
    const float* p1 = s1 + (size_t)b * k1 * N_TOK;
    const float* p2 = s2 + (size_t)b * (K - k0 - k1) * N_TOK;

    constexpr int MT = M / 8;
    float acc[MT][4];
    #pragma unroll
    for (int i = 0; i < MT; i++) { acc[i][0]=0.f; acc[i][1]=0.f; acc[i][2]=0.f; acc[i][3]=0.f; }

    for (int kc = 0; kc < K; kc += 32) {
        #pragma unroll
        for (int it = 0; it < 16; it++) {
            int idx = it * 128 + tid;
            int k = idx >> 6;
            int n = idx & 63;
            int r = kc + k;
            float v;
            if (r < k0)            v = p0[(size_t)r * N_TOK + n0 + n];
            else if (r < k0 + k1)  v = p1[(size_t)(r - k0) * N_TOK + n0 + n];
            else                   v = p2[(size_t)(r - k0 - k1) * N_TOK + n0 + n];
            sX[n * 40 + k] = __float2bfloat16(v);
        }
        __syncthreads();

        #pragma unroll
        for (int ks = 0; ks < 2; ks++) {
            const __nv_bfloat16* qb = sX + (rw + t4) * 40 + ks * 16 + 2 * tm4;
            uint32_t a0 = ld32bf(qb);
            uint32_t a1 = ld32bf(qb + 8 * 40);
            uint32_t a2 = ld32bf(qb + 8);
            uint32_t a3 = ld32bf(qb + 8 * 40 + 8);
            #pragma unroll
            for (int mt = 0; mt < MT; mt++) {
                const __nv_bfloat16* wb = W + (size_t)(mt * 8 + t4) * K + kc + ks * 16 + 2 * tm4;
                uint32_t b0 = ld32bf(wb);
                uint32_t b1 = ld32bf(wb + 8);
                mma_bf16(acc[mt][0], acc[mt][1], acc[mt][2], acc[mt][3],
                         a0, a1, a2, a3, b0, b1);
            }
        }
        __syncthreads();
    }

    int row0 = n0 + rw + t4;
    #pragma unroll
    for (int mt = 0; mt < MT; mt++) {
        int o = mt * 8 + 2 * tm4;
        float bz0 = bias[o], bz1 = bias[o + 1];
        float v0 = acc[mt][0] + bz0;
        float v1 = acc[mt][1] + bz1;
        float v2 = acc[mt][2] + bz0;
        float v3 = acc[mt][3] + bz1;
        if (TOKMAJOR) {
            *reinterpret_cast<__nv_bfloat162*>(out + ((size_t)(b * N_TOK + row0)) * M + o) =
                __floats2bfloat162_rn(v0, v1);
            *reinterpret_cast<__nv_bfloat162*>(out + ((size_t)(b * N_TOK + row0 + 8)) * M + o) =
                __floats2bfloat162_rn(v2, v3);
        } else {
            out[((size_t)(b * M + o)) * N_TOK + row0]         = __float2bfloat16(v0);
            out[((size_t)(b * M + o + 1)) * N_TOK + row0]     = __float2bfloat16(v1);
            out[((size_t)(b * M + o)) * N_TOK + row0 + 8]     = __float2bfloat16(v2);
            out[((size_t)(b * M + o + 1)) * N_TOK + row0 + 8] = __float2bfloat16(v3);
        }
    }
}

// ---------------------------------------------------------------------------
// Flash attention + fused W6 epilogue.
//   8 warps, Q tile = 128 rows, KV tiles of 64, double-buffered cp.async,
//   ldmatrix fragment loads, max-free softmax (logits are tiny by construction),
//   epilogue computes out = W6 @ (O/l) + b6 + x directly (fp32).
// smem: sQ[128][104] | sK[2][64][104] | sV[2][288][72]  = 136,192 B
// ---------------------------------------------------------------------------
#define QT 128
#define KT 64
#define SQ_ELEMS (128 * 104)
#define SK_ELEMS (64 * 104)
#define SV_ELEMS (288 * 72)
#define FLASH_SMEM_BYTES ((SQ_ELEMS + 2 * SK_ELEMS + 2 * SV_ELEMS) * 2)

__global__ void __launch_bounds__(256, 1) flash_kernel(
    const __nv_bfloat16* __restrict__ qt,    // [B, N, 96]
    const __nv_bfloat16* __restrict__ kst,   // [B, N, 96]
    const __nv_bfloat16* __restrict__ vv,    // [B, 288, N]
    const __nv_bfloat16* __restrict__ W6,    // [96, 288]
    const float* __restrict__ b6,
    const float* __restrict__ x,             // [B, 96, N]
    float* __restrict__ out)                 // [B, 96, N]
{
    extern __shared__ __nv_bfloat16 smem[];
    __nv_bfloat16* sQ = smem;

    const int tid = threadIdx.x;
    const int warp = tid >> 5;
    const int lane = tid & 31;
    const int t4 = lane >> 2;
    const int tm4 = lane & 3;
    const int b = blockIdx.y;
    const int n0 = blockIdx.x * QT;
    const int rw = warp * 16;

    const uint32_t smem_b = (uint32_t)__cvta_generic_to_shared(smem);
    const uint32_t sQ_b = smem_b;
    const uint32_t sK_b = smem_b + SQ_ELEMS * 2;
    const uint32_t sV_b = smem_b + (SQ_ELEMS + 2 * SK_ELEMS) * 2;

    // per-lane ldmatrix address components
    const int lg = lane >> 3;        // matrix index 0..3
    const int lr = lane & 7;         // row within matrix
    const int rsel = (lg & 1) * 8 + lr;
    const int csel = (lg >> 1) * 8;
    const uint32_t aAddr0 = sQ_b + ((rw + rsel) * 104 + csel) * 2;
    const uint32_t kAddr0 = sK_b + (rsel * 104 + csel) * 2;
    const uint32_t vAddr0 = sV_b + (rsel * 72 + csel) * 2;

    // ---- load Q tile (plain vectorized loads) ----
    {
        const __nv_bfloat16* qsrc = qt + ((size_t)(b * N_TOK + n0)) * 96;
        #pragma unroll
        for (int it = 0; it < 6; it++) {
            int idx = it * 256 + tid;           // 1536 chunks of 8 bf16
            int row = idx / 12;
            int c8 = idx % 12;
            *reinterpret_cast<uint4*>(sQ + row * 104 + c8 * 8) =
                *reinterpret_cast<const uint4*>(qsrc + (size_t)row * 96 + c8 * 8);
        }
    }

    // ---- async tile loader ----
    const __nv_bfloat16* kbase = kst + ((size_t)b * N_TOK) * 96;
    const __nv_bfloat16* vbase = vv + ((size_t)b * CV) * N_TOK;
    auto issue_tile = [&](int mt_i, int buf) {
        const int m0 = mt_i * KT;
        // K tile: 64 rows x 96 cols -> 64 rows x 12 chunks = 768 chunks
        #pragma unroll
        for (int it = 0; it < 3; it++) {
            int c = it * 256 + tid;
            int row = c / 12, col = c % 12;
            cp16(sK_b + (buf * SK_ELEMS + row * 104 + col * 8) * 2,
                 kbase + (size_t)(m0 + row) * 96 + col * 8);
        }
        // V tile: 288 rows x 64 cols -> 288 rows x 8 chunks = 2304 chunks
        #pragma unroll
        for (int it = 0; it < 9; it++) {
            int c = it * 256 + tid;
            int row = c >> 3, col = c & 7;
            cp16(sV_b + (buf * SV_ELEMS + row * 72 + col * 8) * 2,
                 vbase + (size_t)row * N_TOK + m0 + col * 8);
        }
        cp_commit();
    };

    float o_[36][4];
    #pragma unroll
    for (int i = 0; i < 36; i++) { o_[i][0]=0.f; o_[i][1]=0.f; o_[i][2]=0.f; o_[i][3]=0.f; }
    float l0 = 0.f, l1 = 0.f;

    issue_tile(0, 0);

    int buf = 0;
    for (int mt_i = 0; mt_i < N_TOK / KT; mt_i++) {
        cp_wait0();
        __syncthreads();
        if (mt_i + 1 < N_TOK / KT) issue_tile(mt_i + 1, buf ^ 1);

        const uint32_t kB = kAddr0 + buf * (SK_ELEMS * 2);
        const uint32_t vB = vAddr0 + buf * (SV_ELEMS * 2);

        // ---- S = Q @ K^T ----
        float s[8][4];
        #pragma unroll
        for (int j = 0; j < 8; j++) { s[j][0]=0.f; s[j][1]=0.f; s[j][2]=0.f; s[j][3]=0.f; }
        #pragma unroll
        for (int kk = 0; kk < 6; kk++) {
            uint32_t a0, a1, a2, a3;
            ldsm4(aAddr0 + kk * 32, a0, a1, a2, a3);
            #pragma unroll
            for (int jj = 0; jj < 4; jj++) {
                uint32_t b00, b01, b10, b11;
                ldsm4(kB + jj * (16 * 208) + kk * 32, b00, b01, b10, b11);
                mma_bf16(s[2*jj][0], s[2*jj][1], s[2*jj][2], s[2*jj][3],
                         a0, a1, a2, a3, b00, b10);
                mma_bf16(s[2*jj+1][0], s[2*jj+1][1], s[2*jj+1][2], s[2*jj+1][3],
                         a0, a1, a2, a3, b01, b11);
            }
        }

        // ---- P = exp(S), row sums, repack as A fragments ----
        #pragma unroll
        for (int j = 0; j < 8; j++) {
            s[j][0] = __expf(s[j][0]);
            s[j][1] = __expf(s[j][1]);
            s[j][2] = __expf(s[j][2]);
            s[j][3] = __expf(s[j][3]);
            l0 += s[j][0] + s[j][1];
            l1 += s[j][2] + s[j][3];
        }
        uint32_t pa[4][4];
        #pragma unroll
        for (int g = 0; g < 4; g++) {
            __nv_bfloat162 t0 = __floats2bfloat162_rn(s[2*g][0],   s[2*g][1]);
            __nv_bfloat162 t1 = __floats2bfloat162_rn(s[2*g][2],   s[2*g][3]);
            __nv_bfloat162 t2 = __floats2bfloat162_rn(s[2*g+1][0], s[2*g+1][1]);
            __nv_bfloat162 t3 = __floats2bfloat162_rn(s[2*g+1][2], s[2*g+1][3]);
            pa[g][0] = *reinterpret_cast<uint32_t*>(&t0);
            pa[g][1] = *reinterpret_cast<uint32_t*>(&t1);
            pa[g][2] = *reinterpret_cast<uint32_t*>(&t2);
            pa[g][3] = *reinterpret_cast<uint32_t*>(&t3);
        }

        // ---- O += P @ V^T ----
        #pragma unroll
        for (int g = 0; g < 4; g++) {
            #pragma unroll
            for (int cc = 0; cc < 18; cc++) {
                uint32_t r0, r1, r2, r3;
                ldsm4(vB + cc * (16 * 144) + g * 32, r0, r1, r2, r3);
                mma_bf16(o_[2*cc][0], o_[2*cc][1], o_[2*cc][2], o_[2*cc][3],
                         pa[g][0], pa[g][1], pa[g][2], pa[g][3], r0, r2);
                mma_bf16(o_[2*cc+1][0], o_[2*cc+1][1], o_[2*cc+1][2], o_[2*cc+1][3],
                         pa[g][0], pa[g][1], pa[g][2], pa[g][3], r1, r3);
            }
        }
        buf ^= 1;
        __syncthreads();
    }

    // ---- finalize softmax normalization ----
    l0 += __shfl_xor_sync(0xffffffffu, l0, 1);
    l0 += __shfl_xor_sync(0xffffffffu, l0, 2);
    l1 += __shfl_xor_sync(0xffffffffu, l1, 1);
    l1 += __shfl_xor_sync(0xffffffffu, l1, 2);
    float inv0 = 1.f / l0;
    float inv1 = 1.f / l1;

    // ---- fused epilogue: out = W6 @ res + b6 + x ----
    float acc[12][4];
    #pragma unroll
    for (int i = 0; i < 12; i++) { acc[i][0]=0.f; acc[i][1]=0.f; acc[i][2]=0.f; acc[i][3]=0.f; }

    #pragma unroll
    for (int ks = 0; ks < 18; ks++) {
        __nv_bfloat162 ta0 = __floats2bfloat162_rn(o_[2*ks][0]*inv0,   o_[2*ks][1]*inv0);
        __nv_bfloat162 ta1 = __floats2bfloat162_rn(o_[2*ks][2]*inv1,   o_[2*ks][3]*inv1);
        __nv_bfloat162 ta2 = __floats2bfloat162_rn(o_[2*ks+1][0]*inv0, o_[2*ks+1][1]*inv0);
        __nv_bfloat162 ta3 = __floats2bfloat162_rn(o_[2*ks+1][2]*inv1, o_[2*ks+1][3]*inv1);
        uint32_t a0 = *reinterpret_cast<uint32_t*>(&ta0);
        uint32_t a1 = *reinterpret_cast<uint32_t*>(&ta1);
        uint32_t a2 = *reinterpret_cast<uint32_t*>(&ta2);
        uint32_t a3 = *reinterpret_cast<uint32_t*>(&ta3);
        #pragma unroll
        for (int mt = 0; mt < 12; mt++) {
            const __nv_bfloat16* wb = W6 + (size_t)(mt * 8 + t4) * CV + ks * 16 + 2 * tm4;
            uint32_t b0 = ld32bf(wb);
            uint32_t b1 = ld32bf(wb + 8);
            mma_bf16(acc[mt][0], acc[mt][1], acc[mt][2], acc[mt][3],
                     a0, a1, a2, a3, b0, b1);
        }
    }

    int n = n0 + rw + t4;
    #pragma unroll
    for (int mt = 0; mt < 12; mt++) {
        int o = mt * 8 + 2 * tm4;
        size_t i00 = ((size_t)(b * CC + o)) * N_TOK + n;
        size_t i01 = i00 + N_TOK;
        out[i00]     = acc[mt][0] + b6[o]     + x[i00];
        out[i01]     = acc[mt][1] + b6[o + 1] + x[i01];
        out[i00 + 8] = acc[mt][2] + b6[o]     + x[i00 + 8];
        out[i01 + 8] = acc[mt][3] + b6[o + 1] + x[i01 + 8];
    }
}

// ---------------------------------------------------------------------------
// Launch
// ---------------------------------------------------------------------------
extern "C" void kernel_launch(void* const* d_in, const int* in_sizes, int n_in,
                              void* d_out, int out_size)
{
    const float* context = (const float*)d_in[0];
    const float* h0 = (const float*)d_in[1];
    const float* h1 = (const float*)d_in[2];
    const float* x  = (const float*)d_in[3];
    const float* W1 = (const float*)d_in[4];
    const float* b1 = (const float*)d_in[5];
    const float* W2 = (const float*)d_in[6];
    const float* b2 = (const float*)d_in[7];
    const float* W3 = (const float*)d_in[8];
    const float* b3 = (const float*)d_in[9];
    const float* W4 = (const float*)d_in[10];
    const float* b4 = (const float*)d_in[11];
    const float* W5 = (const float*)d_in[12];
    const float* b5 = (const float*)d_in[13];
    const float* W6 = (const float*)d_in[14];
    const float* b6 = (const float*)d_in[15];
    float* out = (float*)d_out;

    void *pWks, *pBks, *pWv, *pBv, *pWq, *pW6, *pKsum, *pQ, *pV;
    cudaGetSymbolAddress(&pWks, g_Wks);
    cudaGetSymbolAddress(&pBks, g_bks);
    cudaGetSymbolAddress(&pWv, g_Wv);
    cudaGetSymbolAddress(&pBv, g_bv);
    cudaGetSymbolAddress(&pWq, g_Wq);
    cudaGetSymbolAddress(&pW6, g_W6c);
    cudaGetSymbolAddress(&pKsum, g_ksum);
    cudaGetSymbolAddress(&pQ, g_q);
    cudaGetSymbolAddress(&pV, g_v);

    cudaFuncSetAttribute(flash_kernel, cudaFuncAttributeMaxDynamicSharedMemorySize,
                         FLASH_SMEM_BYTES);

    prep_kernel<<<640, 256>>>(W1, b1, W2, b2, W3, b3, W4, b4, W5, W6);

    dim3 pgrid(N_TOK / 64, BATCH);
    proj_kernel<CC, KIN, true><<<pgrid, 128>>>(
        context, 128, h0, 96, h1,
        (const __nv_bfloat16*)pWks, (const float*)pBks, (__nv_bfloat16*)pKsum);
    proj_kernel<CV, KIN, false><<<pgrid, 128>>>(
        context, 128, h0, 96, h1,
        (const __nv_bfloat16*)pWv, (const float*)pBv, (__nv_bfloat16*)pV);
    proj_kernel<CC, CC, true><<<pgrid, 128>>>(
        x, 96, x, 0, x,
        (const __nv_bfloat16*)pWq, b5, (__nv_bfloat16*)pQ);

    dim3 fgrid(N_TOK / QT, BATCH);
    flash_kernel<<<fgrid, 256, FLASH_SMEM_BYTES>>>(
        (const __nv_bfloat16*)pQ, (const __nv_bfloat16*)pKsum,
        (const __nv_bfloat16*)pV, (const __nv_bfloat16*)pW6,
        b6, x, out);
}